// round 1
// baseline (speedup 1.0000x reference)
#include <cuda_runtime.h>
#include <math.h>

#define BB 4
#define CC 64
#define OO 64
#define DD 2
#define HH 128
#define WW 128
#define HW (HH*WW)

// Scratch: offset (B,18,D,H,W) and mask (B,9,D,H,W)
__device__ float g_off[BB*18*DD*HW];
__device__ float g_mask[BB*9*DD*HW];

// ---------------------------------------------------------------------------
// Kernel 1: fused conv3d producing 18 offset channels + 9 mask channels.
// Block: 128 threads = one output row (y) for one (b, od). Grid (128, 2, 4).
// Shared holds weights for a 16-channel input chunk: [cl][dd][tap][28] (27 oc
// padded to 28 for float4 access).
// ---------------------------------------------------------------------------
__global__ __launch_bounds__(128) void conv3d_om_kernel(
    const float* __restrict__ x, const float* __restrict__ ow,
    const float* __restrict__ ob, const float* __restrict__ mw,
    const float* __restrict__ mb)
{
    __shared__ __align__(16) float wsh[16*18*28];
    const int xc = threadIdx.x;
    const int y  = blockIdx.x;
    const int od = blockIdx.y;
    const int b  = blockIdx.z;
    // output depth od uses input depth id with kernel slice kd = id + kdoff
    const int kdoff = (od == 0) ? 1 : 0;

    float acc[28];
#pragma unroll
    for (int o = 0; o < 28; o++) acc[o] = 0.f;

    for (int c0 = 0; c0 < CC; c0 += 16) {
        // cooperative weight load (pad slot o==27 with zero)
        for (int i = xc; i < 16*18*28; i += 128) {
            int o = i % 28;
            int rest = i / 28;                 // cl*18 + dd*9 + tap
            int tap = rest % 9;
            int dd  = (rest / 9) & 1;
            int cl  = rest / 18;
            int c = c0 + cl;
            int kd = dd + kdoff;
            float v = 0.f;
            if (o < 27) {
                v = (o < 18) ? ow[((o*CC + c)*3 + kd)*9 + tap]
                             : mw[(((o-18)*CC + c)*3 + kd)*9 + tap];
            }
            wsh[i] = v;
        }
        __syncthreads();

#pragma unroll 1
        for (int cl = 0; cl < 16; cl++) {
            const float* xb = x + (size_t)((b*CC + c0 + cl)*DD) * HW;
#pragma unroll
            for (int dd = 0; dd < 2; dd++) {
                const float* xd = xb + dd*HW;
#pragma unroll
                for (int ky = 0; ky < 3; ky++) {
                    int yin = y - 1 + ky;
                    bool yv = ((unsigned)yin < (unsigned)HH);
#pragma unroll
                    for (int kx = 0; kx < 3; kx++) {
                        int xin = xc - 1 + kx;
                        float v = (yv && (unsigned)xin < (unsigned)WW)
                                    ? xd[yin*WW + xin] : 0.f;
                        const float4* wp =
                            (const float4*)&wsh[((cl*2 + dd)*9 + ky*3 + kx)*28];
#pragma unroll
                        for (int q = 0; q < 7; q++) {
                            float4 w4 = wp[q];
                            acc[q*4+0] += v * w4.x;
                            acc[q*4+1] += v * w4.y;
                            acc[q*4+2] += v * w4.z;
                            acc[q*4+3] += v * w4.w;
                        }
                    }
                }
            }
        }
        __syncthreads();
    }

    const int pix = y*WW + xc;
#pragma unroll
    for (int ch = 0; ch < 18; ch++)
        g_off[((b*18 + ch)*DD + od)*HW + pix] = acc[ch] + ob[ch];
#pragma unroll
    for (int j = 0; j < 9; j++) {
        float t = acc[18 + j] + mb[j];
        g_mask[((b*9 + j)*DD + od)*HW + pix] = 2.f / (1.f + expf(-t));
    }
}

// ---------------------------------------------------------------------------
// Kernel 2: modulated deformable conv2d, applied per depth slice.
// Block: 128 threads = one output row (y) for one (b, d). Grid (128, 2, 4).
// Each thread owns all 64 output-channel accumulators for its pixel.
// Weights chunked by 16 input channels into shared: wsh[(cl*9+j)*64 + o].
// ---------------------------------------------------------------------------
__global__ __launch_bounds__(128) void deform_kernel(
    const float* __restrict__ x, const float* __restrict__ w0,
    float* __restrict__ out)
{
    __shared__ __align__(16) float wsh[16*9*64];
    const int xc = threadIdx.x;
    const int y  = blockIdx.x;
    const int d  = blockIdx.y;
    const int b  = blockIdx.z;
    const int pix = y*WW + xc;

    float acc[64];
#pragma unroll
    for (int o = 0; o < 64; o++) acc[o] = 0.f;

    for (int c0 = 0; c0 < CC; c0 += 16) {
        // cooperative weight load: wsh[(cl*9+j)*64 + o] = w0[o][c0+cl][j]
        for (int i = xc; i < 16*9*64; i += 128) {
            int o  = i & 63;
            int cj = i >> 6;             // cl*9 + j
            int cl = cj / 9;
            int j  = cj - cl*9;
            wsh[i] = w0[(o*CC + c0 + cl)*9 + j];
        }
        __syncthreads();

#pragma unroll 1
        for (int j = 0; j < 9; j++) {
            float dy = g_off[((b*18 + 2*j    )*DD + d)*HW + pix];
            float dx = g_off[((b*18 + 2*j + 1)*DD + d)*HW + pix];
            float m  = g_mask[((b*9 + j)*DD + d)*HW + pix];
            float py = (float)(y  - 1 + j/3) + dy;
            float px = (float)(xc - 1 + j%3) + dx;
            float fy = floorf(py), fx = floorf(px);
            float ly = py - fy,    lx = px - fx;
            float hy = 1.f - ly,   hx = 1.f - lx;
            int iy0 = (int)fy, ix0 = (int)fx;
            int iy1 = iy0 + 1, ix1 = ix0 + 1;
            bool vy0 = ((unsigned)iy0 < (unsigned)HH);
            bool vy1 = ((unsigned)iy1 < (unsigned)HH);
            bool vx0 = ((unsigned)ix0 < (unsigned)WW);
            bool vx1 = ((unsigned)ix1 < (unsigned)WW);
            float a00 = (vy0 && vx0) ? hy*hx*m : 0.f;
            float a01 = (vy0 && vx1) ? hy*lx*m : 0.f;
            float a10 = (vy1 && vx0) ? ly*hx*m : 0.f;
            float a11 = (vy1 && vx1) ? ly*lx*m : 0.f;
            int yr0 = min(max(iy0, 0), HH-1)*WW;
            int yr1 = min(max(iy1, 0), HH-1)*WW;
            int xr0 = min(max(ix0, 0), WW-1);
            int xr1 = min(max(ix1, 0), WW-1);
            int o00 = yr0 + xr0, o01 = yr0 + xr1;
            int o10 = yr1 + xr0, o11 = yr1 + xr1;

#pragma unroll 2
            for (int cl = 0; cl < 16; cl++) {
                const float* xp = x + (size_t)((b*CC + c0 + cl)*DD + d) * HW;
                float v = a00*xp[o00] + a01*xp[o01] + a10*xp[o10] + a11*xp[o11];
                const float4* wp = (const float4*)&wsh[(cl*9 + j)*64];
#pragma unroll
                for (int q = 0; q < 16; q++) {
                    float4 w4 = wp[q];
                    acc[q*4+0] += v * w4.x;
                    acc[q*4+1] += v * w4.y;
                    acc[q*4+2] += v * w4.z;
                    acc[q*4+3] += v * w4.w;
                }
            }
        }
        __syncthreads();
    }

    float* op = out + (size_t)(b*OO*DD + d) * HW + pix;
#pragma unroll
    for (int o = 0; o < 64; o++)
        op[(size_t)o * DD * HW] = acc[o];
}

// ---------------------------------------------------------------------------
// Launch
// ---------------------------------------------------------------------------
extern "C" void kernel_launch(void* const* d_in, const int* in_sizes, int n_in,
                              void* d_out, int out_size)
{
    const float* x  = (const float*)d_in[0];
    const float* ow = (const float*)d_in[1];
    const float* ob = (const float*)d_in[2];
    const float* mw = (const float*)d_in[3];
    const float* mb = (const float*)d_in[4];
    const float* w0 = (const float*)d_in[5];
    float* out = (float*)d_out;

    dim3 grid(HH, DD, BB);
    conv3d_om_kernel<<<grid, 128>>>(x, ow, ob, mw, mb);
    deform_kernel<<<grid, 128>>>(x, w0, out);
}

// round 3
// speedup vs baseline: 1.5831x; 1.5831x over previous
#include <cuda_runtime.h>
#include <cuda_bf16.h>
#include <math.h>
#include <stdint.h>

#define BB 4
#define CC 64
#define OO 64
#define DD 2
#define HH 128
#define WW 128
#define HW (HH*WW)

// Scratch: offset (B,18,D,H,W) and mask (B,9,D,H,W)
__device__ float g_off[BB*18*DD*HW];
__device__ float g_mask[BB*9*DD*HW];
// Prepacked bf16 weight tiles: per tap j, [oc][ch] row-major, hi and lo.
__device__ __nv_bfloat16 g_Bh[9][64*64];
__device__ __nv_bfloat16 g_Bl[9][64*64];

__device__ __forceinline__ uint32_t smem_to_u32(const void* p) {
    uint32_t a;
    asm("{ .reg .u64 t; cvta.to.shared.u64 t, %1; cvt.u32.u64 %0, t; }"
        : "=r"(a) : "l"(p));
    return a;
}

#define LDMATRIX_X4(r0, r1, r2, r3, addr) \
    asm volatile("ldmatrix.sync.aligned.m8n8.x4.shared.b16 {%0,%1,%2,%3}, [%4];" \
        : "=r"(r0), "=r"(r1), "=r"(r2), "=r"(r3) : "r"(addr))

#define MMA_BF16(c, a0, a1, a2, a3, b0, b1) \
    asm volatile("mma.sync.aligned.m16n8k16.row.col.f32.bf16.bf16.f32 " \
        "{%0,%1,%2,%3}, {%4,%5,%6,%7}, {%8,%9}, {%0,%1,%2,%3};" \
        : "+f"((c)[0]), "+f"((c)[1]), "+f"((c)[2]), "+f"((c)[3]) \
        : "r"(a0), "r"(a1), "r"(a2), "r"(a3), "r"(b0), "r"(b1))

// ---------------------------------------------------------------------------
// Kernel 0: pack w0 -> bf16 hi/lo tiles per tap j (plain [oc][ch] layout)
// ---------------------------------------------------------------------------
__global__ void pack_w_kernel(const float* __restrict__ w0) {
    for (int i = threadIdx.x + blockIdx.x * blockDim.x; i < 9*64*64;
         i += blockDim.x * gridDim.x) {
        int j = i / 4096;
        int r = i - j*4096;
        int o = r >> 6;
        int c = r & 63;
        float v = w0[(o*CC + c)*9 + j];
        __nv_bfloat16 hb = __float2bfloat16(v);
        float l = v - __bfloat162float(hb);
        g_Bh[j][r] = hb;
        g_Bl[j][r] = __float2bfloat16(l);
    }
}

// ---------------------------------------------------------------------------
// Kernel 1: fused conv3d producing 18 offset channels + 9 mask channels.
// (unchanged — next round's target)
// ---------------------------------------------------------------------------
__global__ __launch_bounds__(128) void conv3d_om_kernel(
    const float* __restrict__ x, const float* __restrict__ ow,
    const float* __restrict__ ob, const float* __restrict__ mw,
    const float* __restrict__ mb)
{
    __shared__ __align__(16) float wsh[16*18*28];
    const int xc = threadIdx.x;
    const int y  = blockIdx.x;
    const int od = blockIdx.y;
    const int b  = blockIdx.z;
    const int kdoff = (od == 0) ? 1 : 0;

    float acc[28];
#pragma unroll
    for (int o = 0; o < 28; o++) acc[o] = 0.f;

    for (int c0 = 0; c0 < CC; c0 += 16) {
        for (int i = xc; i < 16*18*28; i += 128) {
            int o = i % 28;
            int rest = i / 28;
            int tap = rest % 9;
            int dd  = (rest / 9) & 1;
            int cl  = rest / 18;
            int c = c0 + cl;
            int kd = dd + kdoff;
            float v = 0.f;
            if (o < 27) {
                v = (o < 18) ? ow[((o*CC + c)*3 + kd)*9 + tap]
                             : mw[(((o-18)*CC + c)*3 + kd)*9 + tap];
            }
            wsh[i] = v;
        }
        __syncthreads();

#pragma unroll 1
        for (int cl = 0; cl < 16; cl++) {
            const float* xb = x + (size_t)((b*CC + c0 + cl)*DD) * HW;
#pragma unroll
            for (int dd = 0; dd < 2; dd++) {
                const float* xd = xb + dd*HW;
#pragma unroll
                for (int ky = 0; ky < 3; ky++) {
                    int yin = y - 1 + ky;
                    bool yv = ((unsigned)yin < (unsigned)HH);
#pragma unroll
                    for (int kx = 0; kx < 3; kx++) {
                        int xin = xc - 1 + kx;
                        float v = (yv && (unsigned)xin < (unsigned)WW)
                                    ? xd[yin*WW + xin] : 0.f;
                        const float4* wp =
                            (const float4*)&wsh[((cl*2 + dd)*9 + ky*3 + kx)*28];
#pragma unroll
                        for (int q = 0; q < 7; q++) {
                            float4 w4 = wp[q];
                            acc[q*4+0] += v * w4.x;
                            acc[q*4+1] += v * w4.y;
                            acc[q*4+2] += v * w4.z;
                            acc[q*4+3] += v * w4.w;
                        }
                    }
                }
            }
        }
        __syncthreads();
    }

    const int pix = y*WW + xc;
#pragma unroll
    for (int ch = 0; ch < 18; ch++)
        g_off[((b*18 + ch)*DD + od)*HW + pix] = acc[ch] + ob[ch];
#pragma unroll
    for (int j = 0; j < 9; j++) {
        float t = acc[18 + j] + mb[j];
        g_mask[((b*9 + j)*DD + od)*HW + pix] = 2.f / (1.f + expf(-t));
    }
}

// ---------------------------------------------------------------------------
// Kernel 2: deformable conv via mma.sync m16n8k16 bf16 split-precision.
// Block: 128 threads = one row (128 pixels) of one (b,d). Grid (128,2,4).
// smem A: [128 pix][72 halfs] (64 ch + 8 pad), hi+lo.
// smem B: [64 oc][72 halfs], hi+lo.
// Each warp owns M=32 pixels (2 m-tiles) x N=64 (8 n-tiles) accumulators.
// ---------------------------------------------------------------------------
#define ASTRIDE_B 144            // bytes per A/B row (72 halfs)
#define SM_A_HI   0
#define SM_A_LO   (128*ASTRIDE_B)            // 18432
#define SM_B_HI   (2*128*ASTRIDE_B)          // 36864
#define SM_B_LO   (SM_B_HI + 64*ASTRIDE_B)   // 46080
#define SM_TOTAL  (SM_B_LO + 64*ASTRIDE_B)   // 55296

__global__ __launch_bounds__(128)
void deform_mma_kernel(const float* __restrict__ x, float* __restrict__ out)
{
    extern __shared__ char smem[];
    const uint32_t smem_u = smem_to_u32(smem);
    const int tid = threadIdx.x;
    const int wid = tid >> 5;
    const int lane = tid & 31;
    const int y   = blockIdx.x;
    const int d   = blockIdx.y;
    const int b   = blockIdx.z;
    const int pix = y*WW + tid;            // thread = pixel x

    float acc[2][8][4];
#pragma unroll
    for (int mt = 0; mt < 2; mt++)
#pragma unroll
        for (int nt = 0; nt < 8; nt++)
#pragma unroll
            for (int q = 0; q < 4; q++) acc[mt][nt][q] = 0.f;

    const float* xbase = x + ((size_t)b*CC*DD + d) * HW;

    // ldmatrix lane-address components (constant across taps)
    const int agrp = lane >> 3;
    const int arow_off = (lane & 7) + ((agrp & 1) << 3);   // + (a col sel)
    const int acol_off = (agrp >> 1) << 4;                 // bytes: 8 halfs = 16B
    const int brow_off = (lane & 7) + ((agrp >> 1) << 3);
    const int bcol_off = (agrp & 1) << 4;

#pragma unroll 1
    for (int j = 0; j < 9; j++) {
        // ---- copy prepacked B tile into padded smem ----
        {
            const uint4* sh = (const uint4*)(g_Bh[j]);
            const uint4* sl = (const uint4*)(g_Bl[j]);
#pragma unroll
            for (int it = 0; it < 4; it++) {
                int u = tid + 128*it;          // unit = 16B = 8 halfs
                int row = u >> 3;
                int seg = u & 7;
                uint32_t dst = row*ASTRIDE_B + seg*16;
                uint4 vh = sh[u];
                uint4 vl = sl[u];
                asm volatile("st.shared.v4.u32 [%0], {%1,%2,%3,%4};"
                    :: "r"(smem_u + SM_B_HI + dst),
                       "r"(vh.x), "r"(vh.y), "r"(vh.z), "r"(vh.w) : "memory");
                asm volatile("st.shared.v4.u32 [%0], {%1,%2,%3,%4};"
                    :: "r"(smem_u + SM_B_LO + dst),
                       "r"(vl.x), "r"(vl.y), "r"(vl.z), "r"(vl.w) : "memory");
            }
        }

        // ---- per-pixel sampling setup ----
        float dy = g_off[((b*18 + 2*j    )*DD + d)*HW + pix];
        float dx = g_off[((b*18 + 2*j + 1)*DD + d)*HW + pix];
        float m  = g_mask[((b*9 + j)*DD + d)*HW + pix];
        float py = (float)(y   - 1 + j/3) + dy;
        float px = (float)(tid - 1 + j%3) + dx;
        float fy = floorf(py), fx = floorf(px);
        float ly = py - fy,    lx = px - fx;
        float hy = 1.f - ly,   hx = 1.f - lx;
        int iy0 = (int)fy, ix0 = (int)fx;
        int iy1 = iy0 + 1, ix1 = ix0 + 1;
        bool vy0 = ((unsigned)iy0 < (unsigned)HH);
        bool vy1 = ((unsigned)iy1 < (unsigned)HH);
        bool vx0 = ((unsigned)ix0 < (unsigned)WW);
        bool vx1 = ((unsigned)ix1 < (unsigned)WW);
        float a00 = (vy0 && vx0) ? hy*hx*m : 0.f;
        float a01 = (vy0 && vx1) ? hy*lx*m : 0.f;
        float a10 = (vy1 && vx0) ? ly*hx*m : 0.f;
        float a11 = (vy1 && vx1) ? ly*lx*m : 0.f;
        int yr0 = min(max(iy0, 0), HH-1)*WW;
        int yr1 = min(max(iy1, 0), HH-1)*WW;
        int xr0 = min(max(ix0, 0), WW-1);
        int xr1 = min(max(ix1, 0), WW-1);
        int o00 = yr0 + xr0, o01 = yr0 + xr1;
        int o10 = yr1 + xr0, o11 = yr1 + xr1;

        const uint32_t arow = (uint32_t)tid * ASTRIDE_B;

        // ---- build A tile: 64 channels, bf16 hi/lo ----
#pragma unroll 2
        for (int c = 0; c < CC; c += 4) {
            float v0, v1, v2, v3;
            {
                const float* xp = xbase + (size_t)(c+0)*(DD*HW);
                v0 = a00*xp[o00] + a01*xp[o01] + a10*xp[o10] + a11*xp[o11];
            }
            {
                const float* xp = xbase + (size_t)(c+1)*(DD*HW);
                v1 = a00*xp[o00] + a01*xp[o01] + a10*xp[o10] + a11*xp[o11];
            }
            {
                const float* xp = xbase + (size_t)(c+2)*(DD*HW);
                v2 = a00*xp[o00] + a01*xp[o01] + a10*xp[o10] + a11*xp[o11];
            }
            {
                const float* xp = xbase + (size_t)(c+3)*(DD*HW);
                v3 = a00*xp[o00] + a01*xp[o01] + a10*xp[o10] + a11*xp[o11];
            }
            __nv_bfloat16 h0 = __float2bfloat16(v0);
            __nv_bfloat16 h1 = __float2bfloat16(v1);
            __nv_bfloat16 h2 = __float2bfloat16(v2);
            __nv_bfloat16 h3 = __float2bfloat16(v3);
            float l0 = v0 - __bfloat162float(h0);
            float l1 = v1 - __bfloat162float(h1);
            float l2 = v2 - __bfloat162float(h2);
            float l3 = v3 - __bfloat162float(h3);
            uint32_t ph0 = (uint32_t)__bfloat16_as_ushort(h0)
                         | ((uint32_t)__bfloat16_as_ushort(h1) << 16);
            uint32_t ph1 = (uint32_t)__bfloat16_as_ushort(h2)
                         | ((uint32_t)__bfloat16_as_ushort(h3) << 16);
            uint32_t pl0, pl1;
            asm("cvt.rn.bf16x2.f32 %0, %1, %2;" : "=r"(pl0) : "f"(l1), "f"(l0));
            asm("cvt.rn.bf16x2.f32 %0, %1, %2;" : "=r"(pl1) : "f"(l3), "f"(l2));
            uint32_t off = arow + (uint32_t)(c*2);
            asm volatile("st.shared.v2.u32 [%0], {%1,%2};"
                         :: "r"(smem_u + SM_A_HI + off), "r"(ph0), "r"(ph1) : "memory");
            asm volatile("st.shared.v2.u32 [%0], {%1,%2};"
                         :: "r"(smem_u + SM_A_LO + off), "r"(pl0), "r"(pl1) : "memory");
        }

        __syncthreads();

        // ---- MMA: 3 precision passes (AhBh, AhBl, AlBh) ----
#pragma unroll
        for (int pass = 0; pass < 3; pass++) {
            const uint32_t Abase = smem_u + ((pass == 2) ? SM_A_LO : SM_A_HI);
            const uint32_t Bbase = smem_u + ((pass == 1) ? SM_B_LO : SM_B_HI);
#pragma unroll
            for (int ks = 0; ks < 4; ks++) {
                uint32_t af[2][4];
#pragma unroll
                for (int mt = 0; mt < 2; mt++) {
                    uint32_t addr = Abase
                        + (uint32_t)(wid*32 + mt*16 + arow_off) * ASTRIDE_B
                        + (uint32_t)(ks*32 + acol_off);
                    LDMATRIX_X4(af[mt][0], af[mt][1], af[mt][2], af[mt][3], addr);
                }
#pragma unroll
                for (int np = 0; np < 4; np++) {
                    uint32_t b0, b1, b2, b3;
                    uint32_t addr = Bbase
                        + (uint32_t)(np*16 + brow_off) * ASTRIDE_B
                        + (uint32_t)(ks*32 + bcol_off);
                    LDMATRIX_X4(b0, b1, b2, b3, addr);
#pragma unroll
                    for (int mt = 0; mt < 2; mt++) {
                        MMA_BF16(acc[mt][np*2],
                                 af[mt][0], af[mt][1], af[mt][2], af[mt][3], b0, b1);
                        MMA_BF16(acc[mt][np*2+1],
                                 af[mt][0], af[mt][1], af[mt][2], af[mt][3], b2, b3);
                    }
                }
            }
        }
        __syncthreads();
    }

    // ---- epilogue: write D fragments directly to gmem ----
#pragma unroll
    for (int mt = 0; mt < 2; mt++) {
        int xr = wid*32 + mt*16 + (lane >> 2);
        float* op0 = out + ((size_t)b*OO*DD + d)*HW + y*WW + xr;
#pragma unroll
        for (int nt = 0; nt < 8; nt++) {
            int oc = nt*8 + 2*(lane & 3);
            op0[(size_t)(oc  )*DD*HW        ] = acc[mt][nt][0];
            op0[(size_t)(oc+1)*DD*HW        ] = acc[mt][nt][1];
            op0[(size_t)(oc  )*DD*HW + 8    ] = acc[mt][nt][2];
            op0[(size_t)(oc+1)*DD*HW + 8    ] = acc[mt][nt][3];
        }
    }
}

// ---------------------------------------------------------------------------
// Launch
// ---------------------------------------------------------------------------
extern "C" void kernel_launch(void* const* d_in, const int* in_sizes, int n_in,
                              void* d_out, int out_size)
{
    const float* x  = (const float*)d_in[0];
    const float* ow = (const float*)d_in[1];
    const float* ob = (const float*)d_in[2];
    const float* mw = (const float*)d_in[3];
    const float* mb = (const float*)d_in[4];
    const float* w0 = (const float*)d_in[5];
    float* out = (float*)d_out;

    static int attr_set = 0;
    if (!attr_set) {
        cudaFuncSetAttribute(deform_mma_kernel,
                             cudaFuncAttributeMaxDynamicSharedMemorySize, SM_TOTAL);
        attr_set = 1;
    }

    dim3 grid(HH, DD, BB);
    pack_w_kernel<<<36, 256>>>(w0);
    conv3d_om_kernel<<<grid, 128>>>(x, ow, ob, mw, mb);
    deform_mma_kernel<<<grid, 128, SM_TOTAL>>>(x, out);
}

// round 6
// speedup vs baseline: 2.7366x; 1.7286x over previous
#include <cuda_runtime.h>
#include <cuda_bf16.h>
#include <math.h>
#include <stdint.h>

#define BB 4
#define CC 64
#define OO 64
#define DD 2
#define HH 128
#define WW 128
#define HW (HH*WW)

// Scratch: offset (B,18,D,H,W) and mask (B,9,D,H,W)
__device__ float g_off[BB*18*DD*HW];
__device__ float g_mask[BB*9*DD*HW];
// Prepacked bf16 deform-weight tiles: per tap j, [oc][ch] row-major, hi and lo.
__device__ __nv_bfloat16 g_Bh[9][64*64];
__device__ __nv_bfloat16 g_Bl[9][64*64];
// Prepacked conv3d offset/mask weights: [od][dd*9+tap][32 oc x 64 ch], hi/lo.
__device__ __nv_bfloat16 g_OWh[2][18][32*64];
__device__ __nv_bfloat16 g_OWl[2][18][32*64];

__device__ __forceinline__ uint32_t smem_to_u32(const void* p) {
    uint32_t a;
    asm("{ .reg .u64 t; cvta.to.shared.u64 t, %1; cvt.u32.u64 %0, t; }"
        : "=r"(a) : "l"(p));
    return a;
}

#define LDMATRIX_X4(r0, r1, r2, r3, addr) \
    asm volatile("ldmatrix.sync.aligned.m8n8.x4.shared.b16 {%0,%1,%2,%3}, [%4];" \
        : "=r"(r0), "=r"(r1), "=r"(r2), "=r"(r3) : "r"(addr))

#define MMA_BF16(c, a0, a1, a2, a3, b0, b1) \
    asm volatile("mma.sync.aligned.m16n8k16.row.col.f32.bf16.bf16.f32 " \
        "{%0,%1,%2,%3}, {%4,%5,%6,%7}, {%8,%9}, {%0,%1,%2,%3};" \
        : "+f"((c)[0]), "+f"((c)[1]), "+f"((c)[2]), "+f"((c)[3]) \
        : "r"(a0), "r"(a1), "r"(a2), "r"(a3), "r"(b0), "r"(b1))

// ---------------------------------------------------------------------------
// Kernel 0: pack all weights -> bf16 hi/lo tiles
// ---------------------------------------------------------------------------
__global__ void pack_w_kernel(const float* __restrict__ w0,
                              const float* __restrict__ ow,
                              const float* __restrict__ mw) {
    const int N1 = 9*4096;          // deform weights
    const int N2 = 2*18*2048;       // conv3d offset/mask weights
    for (int i = threadIdx.x + blockIdx.x * blockDim.x; i < N1 + N2;
         i += blockDim.x * gridDim.x) {
        if (i < N1) {
            int j = i / 4096;
            int r = i - j*4096;
            int o = r >> 6;
            int c = r & 63;
            float v = w0[(o*CC + c)*9 + j];
            __nv_bfloat16 hb = __float2bfloat16(v);
            g_Bh[j][r] = hb;
            g_Bl[j][r] = __float2bfloat16(v - __bfloat162float(hb));
        } else {
            int k = i - N1;
            int od = k / 36864;
            int r2 = k - od*36864;
            int jj = r2 >> 11;          // dd*9 + tap
            int q  = r2 & 2047;
            int o  = q >> 6;
            int c  = q & 63;
            int dd = jj / 9;
            int tap = jj - dd*9;
            int kd = dd + (od == 0 ? 1 : 0);
            float v = 0.f;
            if (o < 18)      v = ow[((o*CC + c)*3 + kd)*9 + tap];
            else if (o < 27) v = mw[(((o-18)*CC + c)*3 + kd)*9 + tap];
            __nv_bfloat16 hb = __float2bfloat16(v);
            g_OWh[od][jj][q] = hb;
            g_OWl[od][jj][q] = __float2bfloat16(v - __bfloat162float(hb));
        }
    }
}

// ---------------------------------------------------------------------------
// Kernel 1: conv3d offset/mask via mma.sync bf16 split-precision.
// Block: 128 threads = one row y of one (b, od). Grid (128, 2, 4).
// Loop jj = dd*9+tap (18 K-chunks of 64 channels each).
// A: [128 pix][72 halfs] hi+lo. B: [32 oc][72 halfs] hi+lo.
// ---------------------------------------------------------------------------
#define ASTRIDE_B 144            // bytes per row (72 halfs: 64 data + 8 pad)
#define CV_A_HI   0
#define CV_A_LO   (128*ASTRIDE_B)            // 18432
#define CV_B_HI   (2*128*ASTRIDE_B)          // 36864
#define CV_B_LO   (CV_B_HI + 32*ASTRIDE_B)   // 41472
#define CV_TOTAL  (CV_B_LO + 32*ASTRIDE_B)   // 46080

__global__ __launch_bounds__(128)
void conv3d_mma_kernel(const float* __restrict__ x,
                       const float* __restrict__ ob,
                       const float* __restrict__ mb)
{
    extern __shared__ char smem[];
    const uint32_t smem_u = smem_to_u32(smem);
    const int tid = threadIdx.x;
    const int wid = tid >> 5;
    const int lane = tid & 31;
    const int y   = blockIdx.x;
    const int od  = blockIdx.y;
    const int b   = blockIdx.z;

    float acc[2][4][4];
#pragma unroll
    for (int mt = 0; mt < 2; mt++)
#pragma unroll
        for (int nt = 0; nt < 4; nt++)
#pragma unroll
            for (int q = 0; q < 4; q++) acc[mt][nt][q] = 0.f;

    const int agrp = lane >> 3;
    const int arow_off = (lane & 7) + ((agrp & 1) << 3);
    const int acol_off = (agrp >> 1) << 4;
    const int brow_off = (lane & 7) + ((agrp >> 1) << 3);
    const int bcol_off = (agrp & 1) << 4;

#pragma unroll 1
    for (int jj = 0; jj < 18; jj++) {
        const int dd  = jj / 9;
        const int tap = jj - dd*9;
        const int ky  = tap / 3;
        const int kx  = tap - ky*3;

        // ---- copy prepacked B tile into padded smem (32 rows x 8 units) ----
        {
            const uint4* sh = (const uint4*)(g_OWh[od][jj]);
            const uint4* sl = (const uint4*)(g_OWl[od][jj]);
#pragma unroll
            for (int it = 0; it < 2; it++) {
                int u = tid + 128*it;
                int row = u >> 3;
                int seg = u & 7;
                uint32_t dst = row*ASTRIDE_B + seg*16;
                uint4 vh = sh[u];
                uint4 vl = sl[u];
                asm volatile("st.shared.v4.u32 [%0], {%1,%2,%3,%4};"
                    :: "r"(smem_u + CV_B_HI + dst),
                       "r"(vh.x), "r"(vh.y), "r"(vh.z), "r"(vh.w) : "memory");
                asm volatile("st.shared.v4.u32 [%0], {%1,%2,%3,%4};"
                    :: "r"(smem_u + CV_B_LO + dst),
                       "r"(vl.x), "r"(vl.y), "r"(vl.z), "r"(vl.w) : "memory");
            }
        }

        // ---- build A tile: shifted x reads, 64 channels ----
        const int yin = y - 1 + ky;
        const int xin = tid - 1 + kx;
        const bool valid = ((unsigned)yin < (unsigned)HH) &&
                           ((unsigned)xin < (unsigned)WW);
        const float* xp0 = x + ((size_t)(b*CC)*DD + dd)*HW + yin*WW + xin;
        const uint32_t arow = (uint32_t)tid * ASTRIDE_B;

#pragma unroll 2
        for (int c = 0; c < CC; c += 4) {
            float v0 = valid ? xp0[(size_t)(c+0)*(DD*HW)] : 0.f;
            float v1 = valid ? xp0[(size_t)(c+1)*(DD*HW)] : 0.f;
            float v2 = valid ? xp0[(size_t)(c+2)*(DD*HW)] : 0.f;
            float v3 = valid ? xp0[(size_t)(c+3)*(DD*HW)] : 0.f;
            __nv_bfloat16 h0 = __float2bfloat16(v0);
            __nv_bfloat16 h1 = __float2bfloat16(v1);
            __nv_bfloat16 h2 = __float2bfloat16(v2);
            __nv_bfloat16 h3 = __float2bfloat16(v3);
            float l0 = v0 - __bfloat162float(h0);
            float l1 = v1 - __bfloat162float(h1);
            float l2 = v2 - __bfloat162float(h2);
            float l3 = v3 - __bfloat162float(h3);
            uint32_t ph0 = (uint32_t)__bfloat16_as_ushort(h0)
                         | ((uint32_t)__bfloat16_as_ushort(h1) << 16);
            uint32_t ph1 = (uint32_t)__bfloat16_as_ushort(h2)
                         | ((uint32_t)__bfloat16_as_ushort(h3) << 16);
            uint32_t pl0, pl1;
            asm("cvt.rn.bf16x2.f32 %0, %1, %2;" : "=r"(pl0) : "f"(l1), "f"(l0));
            asm("cvt.rn.bf16x2.f32 %0, %1, %2;" : "=r"(pl1) : "f"(l3), "f"(l2));
            uint32_t off = arow + (uint32_t)(c*2);
            asm volatile("st.shared.v2.u32 [%0], {%1,%2};"
                         :: "r"(smem_u + CV_A_HI + off), "r"(ph0), "r"(ph1) : "memory");
            asm volatile("st.shared.v2.u32 [%0], {%1,%2};"
                         :: "r"(smem_u + CV_A_LO + off), "r"(pl0), "r"(pl1) : "memory");
        }

        __syncthreads();

        // ---- MMA: 3 precision passes (AhBh, AhBl, AlBh) ----
#pragma unroll
        for (int pass = 0; pass < 3; pass++) {
            const uint32_t Abase = smem_u + ((pass == 2) ? CV_A_LO : CV_A_HI);
            const uint32_t Bbase = smem_u + ((pass == 1) ? CV_B_LO : CV_B_HI);
#pragma unroll
            for (int ks = 0; ks < 4; ks++) {
                uint32_t af[2][4];
#pragma unroll
                for (int mt = 0; mt < 2; mt++) {
                    uint32_t addr = Abase
                        + (uint32_t)(wid*32 + mt*16 + arow_off) * ASTRIDE_B
                        + (uint32_t)(ks*32 + acol_off);
                    LDMATRIX_X4(af[mt][0], af[mt][1], af[mt][2], af[mt][3], addr);
                }
#pragma unroll
                for (int np = 0; np < 2; np++) {
                    uint32_t b0, b1, b2, b3;
                    uint32_t addr = Bbase
                        + (uint32_t)(np*16 + brow_off) * ASTRIDE_B
                        + (uint32_t)(ks*32 + bcol_off);
                    LDMATRIX_X4(b0, b1, b2, b3, addr);
#pragma unroll
                    for (int mt = 0; mt < 2; mt++) {
                        MMA_BF16(acc[mt][np*2],
                                 af[mt][0], af[mt][1], af[mt][2], af[mt][3], b0, b1);
                        MMA_BF16(acc[mt][np*2+1],
                                 af[mt][0], af[mt][1], af[mt][2], af[mt][3], b2, b3);
                    }
                }
            }
        }
        __syncthreads();
    }

    // ---- epilogue: bias + sigmoid, write g_off / g_mask ----
#pragma unroll
    for (int mt = 0; mt < 2; mt++) {
        int prow = wid*32 + mt*16 + (lane >> 2);
#pragma unroll
        for (int nt = 0; nt < 4; nt++) {
            int oc0 = nt*8 + 2*(lane & 3);
#pragma unroll
            for (int q = 0; q < 4; q++) {
                int oc = oc0 + (q & 1);
                int p  = prow + ((q >> 1) << 3);
                float v = acc[mt][nt][q];
                int pixo = y*WW + p;
                if (oc < 18) {
                    g_off[((b*18 + oc)*DD + od)*HW + pixo] = v + ob[oc];
                } else if (oc < 27) {
                    float t = v + mb[oc - 18];
                    g_mask[((b*9 + oc - 18)*DD + od)*HW + pixo] =
                        2.f / (1.f + expf(-t));
                }
            }
        }
    }
}

// ---------------------------------------------------------------------------
// Kernel 2: deformable conv via mma.sync m16n8k16 bf16 split-precision.
// (unchanged from R3 — known good)
// ---------------------------------------------------------------------------
#define SM_A_HI   0
#define SM_A_LO   (128*ASTRIDE_B)            // 18432
#define SM_B_HI   (2*128*ASTRIDE_B)          // 36864
#define SM_B_LO   (SM_B_HI + 64*ASTRIDE_B)   // 46080
#define SM_TOTAL  (SM_B_LO + 64*ASTRIDE_B)   // 55296

__global__ __launch_bounds__(128)
void deform_mma_kernel(const float* __restrict__ x, float* __restrict__ out)
{
    extern __shared__ char smem[];
    const uint32_t smem_u = smem_to_u32(smem);
    const int tid = threadIdx.x;
    const int wid = tid >> 5;
    const int lane = tid & 31;
    const int y   = blockIdx.x;
    const int d   = blockIdx.y;
    const int b   = blockIdx.z;
    const int pix = y*WW + tid;

    float acc[2][8][4];
#pragma unroll
    for (int mt = 0; mt < 2; mt++)
#pragma unroll
        for (int nt = 0; nt < 8; nt++)
#pragma unroll
            for (int q = 0; q < 4; q++) acc[mt][nt][q] = 0.f;

    const float* xbase = x + ((size_t)b*CC*DD + d) * HW;

    const int agrp = lane >> 3;
    const int arow_off = (lane & 7) + ((agrp & 1) << 3);
    const int acol_off = (agrp >> 1) << 4;
    const int brow_off = (lane & 7) + ((agrp >> 1) << 3);
    const int bcol_off = (agrp & 1) << 4;

#pragma unroll 1
    for (int j = 0; j < 9; j++) {
        {
            const uint4* sh = (const uint4*)(g_Bh[j]);
            const uint4* sl = (const uint4*)(g_Bl[j]);
#pragma unroll
            for (int it = 0; it < 4; it++) {
                int u = tid + 128*it;
                int row = u >> 3;
                int seg = u & 7;
                uint32_t dst = row*ASTRIDE_B + seg*16;
                uint4 vh = sh[u];
                uint4 vl = sl[u];
                asm volatile("st.shared.v4.u32 [%0], {%1,%2,%3,%4};"
                    :: "r"(smem_u + SM_B_HI + dst),
                       "r"(vh.x), "r"(vh.y), "r"(vh.z), "r"(vh.w) : "memory");
                asm volatile("st.shared.v4.u32 [%0], {%1,%2,%3,%4};"
                    :: "r"(smem_u + SM_B_LO + dst),
                       "r"(vl.x), "r"(vl.y), "r"(vl.z), "r"(vl.w) : "memory");
            }
        }

        float dy = g_off[((b*18 + 2*j    )*DD + d)*HW + pix];
        float dx = g_off[((b*18 + 2*j + 1)*DD + d)*HW + pix];
        float m  = g_mask[((b*9 + j)*DD + d)*HW + pix];
        float py = (float)(y   - 1 + j/3) + dy;
        float px = (float)(tid - 1 + j%3) + dx;
        float fy = floorf(py), fx = floorf(px);
        float ly = py - fy,    lx = px - fx;
        float hy = 1.f - ly,   hx = 1.f - lx;
        int iy0 = (int)fy, ix0 = (int)fx;
        int iy1 = iy0 + 1, ix1 = ix0 + 1;
        bool vy0 = ((unsigned)iy0 < (unsigned)HH);
        bool vy1 = ((unsigned)iy1 < (unsigned)HH);
        bool vx0 = ((unsigned)ix0 < (unsigned)WW);
        bool vx1 = ((unsigned)ix1 < (unsigned)WW);
        float a00 = (vy0 && vx0) ? hy*hx*m : 0.f;
        float a01 = (vy0 && vx1) ? hy*lx*m : 0.f;
        float a10 = (vy1 && vx0) ? ly*hx*m : 0.f;
        float a11 = (vy1 && vx1) ? ly*lx*m : 0.f;
        int yr0 = min(max(iy0, 0), HH-1)*WW;
        int yr1 = min(max(iy1, 0), HH-1)*WW;
        int xr0 = min(max(ix0, 0), WW-1);
        int xr1 = min(max(ix1, 0), WW-1);
        int o00 = yr0 + xr0, o01 = yr0 + xr1;
        int o10 = yr1 + xr0, o11 = yr1 + xr1;

        const uint32_t arow = (uint32_t)tid * ASTRIDE_B;

#pragma unroll 2
        for (int c = 0; c < CC; c += 4) {
            float v0, v1, v2, v3;
            {
                const float* xp = xbase + (size_t)(c+0)*(DD*HW);
                v0 = a00*xp[o00] + a01*xp[o01] + a10*xp[o10] + a11*xp[o11];
            }
            {
                const float* xp = xbase + (size_t)(c+1)*(DD*HW);
                v1 = a00*xp[o00] + a01*xp[o01] + a10*xp[o10] + a11*xp[o11];
            }
            {
                const float* xp = xbase + (size_t)(c+2)*(DD*HW);
                v2 = a00*xp[o00] + a01*xp[o01] + a10*xp[o10] + a11*xp[o11];
            }
            {
                const float* xp = xbase + (size_t)(c+3)*(DD*HW);
                v3 = a00*xp[o00] + a01*xp[o01] + a10*xp[o10] + a11*xp[o11];
            }
            __nv_bfloat16 h0 = __float2bfloat16(v0);
            __nv_bfloat16 h1 = __float2bfloat16(v1);
            __nv_bfloat16 h2 = __float2bfloat16(v2);
            __nv_bfloat16 h3 = __float2bfloat16(v3);
            float l0 = v0 - __bfloat162float(h0);
            float l1 = v1 - __bfloat162float(h1);
            float l2 = v2 - __bfloat162float(h2);
            float l3 = v3 - __bfloat162float(h3);
            uint32_t ph0 = (uint32_t)__bfloat16_as_ushort(h0)
                         | ((uint32_t)__bfloat16_as_ushort(h1) << 16);
            uint32_t ph1 = (uint32_t)__bfloat16_as_ushort(h2)
                         | ((uint32_t)__bfloat16_as_ushort(h3) << 16);
            uint32_t pl0, pl1;
            asm("cvt.rn.bf16x2.f32 %0, %1, %2;" : "=r"(pl0) : "f"(l1), "f"(l0));
            asm("cvt.rn.bf16x2.f32 %0, %1, %2;" : "=r"(pl1) : "f"(l3), "f"(l2));
            uint32_t off = arow + (uint32_t)(c*2);
            asm volatile("st.shared.v2.u32 [%0], {%1,%2};"
                         :: "r"(smem_u + SM_A_HI + off), "r"(ph0), "r"(ph1) : "memory");
            asm volatile("st.shared.v2.u32 [%0], {%1,%2};"
                         :: "r"(smem_u + SM_A_LO + off), "r"(pl0), "r"(pl1) : "memory");
        }

        __syncthreads();

#pragma unroll
        for (int pass = 0; pass < 3; pass++) {
            const uint32_t Abase = smem_u + ((pass == 2) ? SM_A_LO : SM_A_HI);
            const uint32_t Bbase = smem_u + ((pass == 1) ? SM_B_LO : SM_B_HI);
#pragma unroll
            for (int ks = 0; ks < 4; ks++) {
                uint32_t af[2][4];
#pragma unroll
                for (int mt = 0; mt < 2; mt++) {
                    uint32_t addr = Abase
                        + (uint32_t)(wid*32 + mt*16 + arow_off) * ASTRIDE_B
                        + (uint32_t)(ks*32 + acol_off);
                    LDMATRIX_X4(af[mt][0], af[mt][1], af[mt][2], af[mt][3], addr);
                }
#pragma unroll
                for (int np = 0; np < 4; np++) {
                    uint32_t b0, b1, b2, b3;
                    uint32_t addr = Bbase
                        + (uint32_t)(np*16 + brow_off) * ASTRIDE_B
                        + (uint32_t)(ks*32 + bcol_off);
                    LDMATRIX_X4(b0, b1, b2, b3, addr);
#pragma unroll
                    for (int mt = 0; mt < 2; mt++) {
                        MMA_BF16(acc[mt][np*2],
                                 af[mt][0], af[mt][1], af[mt][2], af[mt][3], b0, b1);
                        MMA_BF16(acc[mt][np*2+1],
                                 af[mt][0], af[mt][1], af[mt][2], af[mt][3], b2, b3);
                    }
                }
            }
        }
        __syncthreads();
    }

#pragma unroll
    for (int mt = 0; mt < 2; mt++) {
        int xr = wid*32 + mt*16 + (lane >> 2);
        float* op0 = out + ((size_t)b*OO*DD + d)*HW + y*WW + xr;
#pragma unroll
        for (int nt = 0; nt < 8; nt++) {
            int oc = nt*8 + 2*(lane & 3);
            op0[(size_t)(oc  )*DD*HW        ] = acc[mt][nt][0];
            op0[(size_t)(oc+1)*DD*HW        ] = acc[mt][nt][1];
            op0[(size_t)(oc  )*DD*HW + 8    ] = acc[mt][nt][2];
            op0[(size_t)(oc+1)*DD*HW + 8    ] = acc[mt][nt][3];
        }
    }
}

// ---------------------------------------------------------------------------
// Launch
// ---------------------------------------------------------------------------
extern "C" void kernel_launch(void* const* d_in, const int* in_sizes, int n_in,
                              void* d_out, int out_size)
{
    const float* x  = (const float*)d_in[0];
    const float* ow = (const float*)d_in[1];
    const float* ob = (const float*)d_in[2];
    const float* mw = (const float*)d_in[3];
    const float* mb = (const float*)d_in[4];
    const float* w0 = (const float*)d_in[5];
    float* out = (float*)d_out;

    cudaFuncSetAttribute(deform_mma_kernel,
                         cudaFuncAttributeMaxDynamicSharedMemorySize, SM_TOTAL);
    cudaFuncSetAttribute(conv3d_mma_kernel,
                         cudaFuncAttributeMaxDynamicSharedMemorySize, CV_TOTAL);

    dim3 grid(HH, DD, BB);
    pack_w_kernel<<<120, 256>>>(w0, ow, mw);
    conv3d_mma_kernel<<<grid, 128, CV_TOTAL>>>(x, ob, mb);
    deform_mma_kernel<<<grid, 128, SM_TOTAL>>>(x, out);
}